// round 2
// baseline (speedup 1.0000x reference)
#include <cuda_runtime.h>
#include <math.h>

#define B_   2
#define N_   16384
#define C_   512
#define H_   8
#define D_   64
#define M_   64
#define SC_  64
#define BH_  (B_ * H_)

__device__ float g_xmid[(size_t)BH_ * N_ * D_];
__device__ float g_k   [(size_t)BH_ * N_ * D_];
__device__ float g_v   [(size_t)BH_ * N_ * D_];
__device__ float g_q   [(size_t)BH_ * N_ * D_];
__device__ float g_S   [(size_t)BH_ * M_ * N_];
__device__ float g_rmax[BH_ * M_];
__device__ float g_rinv[BH_ * M_];
__device__ float g_lat [BH_ * M_ * D_];
__device__ float g_kc  [BH_ * SC_ * D_];
__device__ float g_vc  [BH_ * SC_ * D_];
__device__ float g_mixed[(size_t)B_ * N_ * C_];

// ---------------- 32768x512x512 GEMM (C = A @ W^T + b) ----------------
// MODE 1: A = Ain(x), scatter to g_xmid(B,H,N,D).  MODE 0: A = g_mixed, out row-major.
template<int MODE>
__global__ void __launch_bounds__(256) gemm512_kernel(const float* __restrict__ Ain,
                                                      const float* __restrict__ W,
                                                      const float* __restrict__ bias,
                                                      float* __restrict__ Cout)
{
    __shared__ float As[16][128];
    __shared__ float Bs[16][128];
    const float* A = (MODE == 0) ? (const float*)g_mixed : Ain;
    const int m0 = blockIdx.y * 128, n0 = blockIdx.x * 128;
    const int tid = threadIdx.x;
    const int rx = tid & 15, ry = tid >> 4;
    const int lr = tid >> 2, lc = (tid & 3) << 2;

    float acc[2][2][4][4];
#pragma unroll
    for (int p = 0; p < 2; p++)
#pragma unroll
        for (int q = 0; q < 2; q++)
#pragma unroll
            for (int i = 0; i < 4; i++)
#pragma unroll
                for (int j = 0; j < 4; j++) acc[p][q][i][j] = 0.f;

    const float* Ap = A + (size_t)(m0 + lr) * C_ + lc;
    const float* Wp = W + (size_t)(n0 + lr) * C_ + lc;

    for (int k0 = 0; k0 < C_; k0 += 16) {
        float4 a0 = *(const float4*)(Ap + k0);
        float4 a1 = *(const float4*)(Ap + (size_t)64 * C_ + k0);
        float4 b0 = *(const float4*)(Wp + k0);
        float4 b1 = *(const float4*)(Wp + (size_t)64 * C_ + k0);
        __syncthreads();
        As[lc+0][lr] = a0.x; As[lc+1][lr] = a0.y; As[lc+2][lr] = a0.z; As[lc+3][lr] = a0.w;
        As[lc+0][lr+64] = a1.x; As[lc+1][lr+64] = a1.y; As[lc+2][lr+64] = a1.z; As[lc+3][lr+64] = a1.w;
        Bs[lc+0][lr] = b0.x; Bs[lc+1][lr] = b0.y; Bs[lc+2][lr] = b0.z; Bs[lc+3][lr] = b0.w;
        Bs[lc+0][lr+64] = b1.x; Bs[lc+1][lr+64] = b1.y; Bs[lc+2][lr+64] = b1.z; Bs[lc+3][lr+64] = b1.w;
        __syncthreads();
#pragma unroll
        for (int kk = 0; kk < 16; kk++) {
            float4 av0 = *(const float4*)&As[kk][ry * 4];
            float4 av1 = *(const float4*)&As[kk][64 + ry * 4];
            float4 bv0 = *(const float4*)&Bs[kk][rx * 4];
            float4 bv1 = *(const float4*)&Bs[kk][64 + rx * 4];
            float ar[2][4] = {{av0.x,av0.y,av0.z,av0.w},{av1.x,av1.y,av1.z,av1.w}};
            float br[2][4] = {{bv0.x,bv0.y,bv0.z,bv0.w},{bv1.x,bv1.y,bv1.z,bv1.w}};
#pragma unroll
            for (int p = 0; p < 2; p++)
#pragma unroll
                for (int i = 0; i < 4; i++)
#pragma unroll
                    for (int q = 0; q < 2; q++)
#pragma unroll
                        for (int j = 0; j < 4; j++)
                            acc[p][q][i][j] = fmaf(ar[p][i], br[q][j], acc[p][q][i][j]);
        }
    }
#pragma unroll
    for (int p = 0; p < 2; p++)
#pragma unroll
        for (int i = 0; i < 4; i++) {
            const int row = m0 + p * 64 + ry * 4 + i;
#pragma unroll
            for (int q = 0; q < 2; q++) {
                const int col = n0 + q * 64 + rx * 4;
                float4 v4;
                v4.x = acc[p][q][i][0] + __ldg(&bias[col+0]);
                v4.y = acc[p][q][i][1] + __ldg(&bias[col+1]);
                v4.z = acc[p][q][i][2] + __ldg(&bias[col+2]);
                v4.w = acc[p][q][i][3] + __ldg(&bias[col+3]);
                if (MODE == 0) {
                    *(float4*)&Cout[(size_t)row * C_ + col] = v4;
                } else {
                    const int b = row >> 14, n = row & (N_ - 1);
                    const int h = col >> 6, d = col & 63;
                    *(float4*)&g_xmid[(((size_t)(b * H_ + h)) * N_ + n) * D_ + d] = v4;
                }
            }
        }
}

// ---------------- k/v/q(head) projections, K=64, 192 outputs ----------------
__global__ void __launch_bounds__(256) kvq_kernel(const float* __restrict__ Wk, const float* __restrict__ bk,
                                                  const float* __restrict__ Wv, const float* __restrict__ bv,
                                                  const float* __restrict__ Wq, const float* __restrict__ bq)
{
    extern __shared__ float sm[];
    float* xm_s   = sm;                 // 128 x 68
    float* W_sT   = sm + 8704;          // [64][192]
    float* bias_s = W_sT + 64 * 192;    // 192

    const int bh = blockIdx.y, t0 = blockIdx.x * 128, tid = threadIdx.x;
    for (int i = tid; i < 4096; i += 256) {
        const int d = i >> 6, c = i & 63;
        W_sT[c*192 + d]       = Wk[i];
        W_sT[c*192 + 64 + d]  = Wv[i];
        W_sT[c*192 + 128 + d] = Wq[i];
    }
    if (tid < 64) { bias_s[tid] = bk[tid]; bias_s[64+tid] = bv[tid]; bias_s[128+tid] = bq[tid]; }
    const float* xp = g_xmid + ((size_t)bh * N_ + t0) * D_;
    for (int i = tid * 4; i < 8192; i += 1024) {
        const int rr = i >> 6, dd = i & 63;
        *(float4*)&xm_s[rr*68+dd] = *(const float4*)(xp + i);
    }
    __syncthreads();

    const int rx = tid & 15, ry = tid >> 4;
    float acc[8][12];
#pragma unroll
    for (int i = 0; i < 8; i++)
#pragma unroll
        for (int j = 0; j < 12; j++) acc[i][j] = 0.f;
#pragma unroll 4
    for (int kk = 0; kk < 64; kk++) {
        float a[8];
#pragma unroll
        for (int i = 0; i < 8; i++) a[i] = xm_s[(ry*8+i)*68 + kk];
        const float* wr = &W_sT[kk*192 + rx*12];
        float4 b0 = *(const float4*)(wr), b1 = *(const float4*)(wr+4), b2 = *(const float4*)(wr+8);
        float bb[12] = {b0.x,b0.y,b0.z,b0.w,b1.x,b1.y,b1.z,b1.w,b2.x,b2.y,b2.z,b2.w};
#pragma unroll
        for (int i = 0; i < 8; i++)
#pragma unroll
            for (int j = 0; j < 12; j++) acc[i][j] = fmaf(a[i], bb[j], acc[i][j]);
    }
    const size_t rowbase = (size_t)bh * N_ + t0;
#pragma unroll
    for (int i = 0; i < 8; i++) {
        const size_t row = rowbase + ry*8 + i;
#pragma unroll
        for (int j = 0; j < 12; j++) {
            const int col = rx*12 + j, mat = col >> 6, d = col & 63;
            float* op = (mat == 0) ? g_k : (mat == 1) ? g_v : g_q;
            op[row * D_ + d] = acc[i][j] + bias_s[col];
        }
    }
}

// ---------------- context kc/vc projection ----------------
__global__ void __launch_bounds__(256) ctx_kernel(const float* __restrict__ ctx,
                                                  const float* __restrict__ Wck, const float* __restrict__ bck,
                                                  const float* __restrict__ Wcv, const float* __restrict__ bcv)
{
    __shared__ float WkT[4096], WvT[4096];
    const int bh = blockIdx.x, tid = threadIdx.x;
    for (int i = tid; i < 4096; i += 256) {
        const int d = i >> 6, c = i & 63;
        WkT[c*64+d] = Wck[i];
        WvT[c*64+d] = Wcv[i];
    }
    __syncthreads();
    const float* cp = ctx + (size_t)bh * 4096;
    for (int o = tid; o < 4096; o += 256) {
        const int s = o >> 6, d = o & 63;
        float ak = bck[d], av = bcv[d];
#pragma unroll 8
        for (int c = 0; c < 64; c++) {
            const float xv = __ldg(&cp[s*64+c]);
            ak = fmaf(xv, WkT[c*64+d], ak);
            av = fmaf(xv, WvT[c*64+d], av);
        }
        g_kc[bh*4096 + o] = ak;
        g_vc[bh*4096 + o] = av;
    }
}

// ---------------- encode logits S[bh][m][n] = qg[h][m] . k[bh][n] ----------------
__global__ void __launch_bounds__(256) enc_logits_kernel(const float* __restrict__ qg)
{
    __shared__ float qgT[4096];   // [d][m]
    __shared__ float kT[8192];    // [d][n] stride 128
    const int bh = blockIdx.y, h = bh & (H_-1);
    const int t0 = blockIdx.x * 128, tid = threadIdx.x;
    for (int i = tid; i < 4096; i += 256) {
        const int m = i >> 6, d = i & 63;
        qgT[d*64+m] = qg[h*4096 + i];
    }
    const float* kp = g_k + ((size_t)bh * N_ + t0) * D_;
    {
        const int n = tid & 127;
        for (int dg = tid >> 7; dg < 16; dg += 2) {
            float4 v4 = *(const float4*)(kp + n*64 + dg*4);
            kT[(dg*4+0)*128+n] = v4.x; kT[(dg*4+1)*128+n] = v4.y;
            kT[(dg*4+2)*128+n] = v4.z; kT[(dg*4+3)*128+n] = v4.w;
        }
    }
    __syncthreads();
    const int rx = tid & 15, ry = tid >> 4;
    float acc[4][8];
#pragma unroll
    for (int i = 0; i < 4; i++)
#pragma unroll
        for (int j = 0; j < 8; j++) acc[i][j] = 0.f;
#pragma unroll 4
    for (int kk = 0; kk < 64; kk++) {
        float4 a4 = *(const float4*)&qgT[kk*64 + ry*4];
        float4 b0 = *(const float4*)&kT[kk*128 + rx*8];
        float4 b1 = *(const float4*)&kT[kk*128 + rx*8 + 4];
        float av[4] = {a4.x,a4.y,a4.z,a4.w};
        float bv[8] = {b0.x,b0.y,b0.z,b0.w,b1.x,b1.y,b1.z,b1.w};
#pragma unroll
        for (int i = 0; i < 4; i++)
#pragma unroll
            for (int j = 0; j < 8; j++) acc[i][j] = fmaf(av[i], bv[j], acc[i][j]);
    }
    float* Sp = g_S + (size_t)bh * M_ * N_ + t0;
#pragma unroll
    for (int i = 0; i < 4; i++) {
        const int m = ry*4 + i;
        *(float4*)&Sp[(size_t)m*N_ + rx*8]     = make_float4(acc[i][0],acc[i][1],acc[i][2],acc[i][3]);
        *(float4*)&Sp[(size_t)m*N_ + rx*8 + 4] = make_float4(acc[i][4],acc[i][5],acc[i][6],acc[i][7]);
    }
}

// ---------------- online row max/sum over N ----------------
__global__ void __launch_bounds__(256) softmax_stats_kernel()
{
    const int r = blockIdx.x;
    const float* Sp = g_S + (size_t)r * N_;
    const int tid = threadIdx.x;
    float mx = -1e30f, s = 0.f;
    for (int n = tid; n < N_; n += 256) {
        const float x = Sp[n];
        const float nm = fmaxf(mx, x);
        s = s * __expf(mx - nm) + __expf(x - nm);
        mx = nm;
    }
    __shared__ float smx[256], ssm[256];
    smx[tid] = mx; ssm[tid] = s;
    __syncthreads();
    for (int off = 128; off; off >>= 1) {
        if (tid < off) {
            const float m2 = smx[tid+off], s2 = ssm[tid+off];
            const float Mv = fmaxf(smx[tid], m2);
            ssm[tid] = ssm[tid]*__expf(smx[tid]-Mv) + s2*__expf(m2-Mv);
            smx[tid] = Mv;
        }
        __syncthreads();
    }
    if (tid == 0) { g_rmax[r] = smx[0]; g_rinv[r] = 1.f / ssm[0]; }
}

__global__ void zero_lat_kernel()
{
    const int i = blockIdx.x * 256 + threadIdx.x;
    if (i < BH_*M_*D_) g_lat[i] = 0.f;
}

// ---------------- latent[m][d] += softmax(S) @ v (split-K, 16 blocks per bh) ----------------
__global__ void __launch_bounds__(256) latent_kernel()
{
    extern __shared__ float sm[];
    float* pT  = sm;          // [128 n][68] (m-minor)
    float* v_s = sm + 8704;   // [128 n][64]
    const int bh = blockIdx.y, tid = threadIdx.x;
    const int rx = tid & 15, ry = tid >> 4;
    float acc[4][4];
#pragma unroll
    for (int i = 0; i < 4; i++)
#pragma unroll
        for (int j = 0; j < 4; j++) acc[i][j] = 0.f;

    for (int sub = 0; sub < 8; sub++) {
        const int nb = blockIdx.x * 1024 + sub * 128;
        __syncthreads();
        const float* Sp = g_S + (size_t)bh * M_ * N_ + nb;
        for (int i = tid; i < 8192; i += 256) {
            const int m = i >> 7, n = i & 127;
            const float x = Sp[(size_t)m*N_ + n];
            pT[n*68 + m] = __expf(x - g_rmax[bh*64+m]) * g_rinv[bh*64+m];
        }
        const float* vp = g_v + ((size_t)bh * N_ + nb) * D_;
        for (int i = tid*4; i < 8192; i += 1024) *(float4*)(v_s + i) = *(const float4*)(vp + i);
        __syncthreads();
#pragma unroll 2
        for (int nn = 0; nn < 128; nn++) {
            float4 a4 = *(const float4*)&pT[nn*68 + ry*4];
            float4 b4 = *(const float4*)&v_s[nn*64 + rx*4];
            float av[4] = {a4.x,a4.y,a4.z,a4.w}, bv[4] = {b4.x,b4.y,b4.z,b4.w};
#pragma unroll
            for (int i = 0; i < 4; i++)
#pragma unroll
                for (int j = 0; j < 4; j++) acc[i][j] = fmaf(av[i], bv[j], acc[i][j]);
        }
    }
    float* lat = g_lat + bh * 4096;
#pragma unroll
    for (int i = 0; i < 4; i++)
#pragma unroll
        for (int j = 0; j < 4; j++)
            atomicAdd(&lat[(ry*4+i)*64 + rx*4 + j], acc[i][j]);
}

// ---------------- fused decode + cross + sigmoid gate ----------------
__global__ void __launch_bounds__(256) dec_cross_kernel(const float* __restrict__ qg,
                                                        const float* __restrict__ smix)
{
    extern __shared__ float sm[];
    float* tile = sm;            // 128 x 68
    float* P    = sm + 8704;     // 128 x 66
    float* mA   = sm + 17152;    // 64 x 64
    float* mB   = sm + 21248;    // 64 x 64    total 25344 floats
    const int bh = blockIdx.y, b = bh >> 3, h = bh & 7;
    const int n0 = blockIdx.x * 128, tid = threadIdx.x;
    const int r = tid >> 1, half = tid & 1, base = half * 32;
    const float w = 1.f / (1.f + __expf(-smix[0]));
    float selfv[32];

    for (int ph = 0; ph < 2; ph++) {
        const float* tsrc = (ph ? g_q : g_k) + ((size_t)bh * N_ + n0) * D_;
        const float* Asrc = ph ? (g_kc + bh*4096) : (qg + h*4096);
        const float* Bsrc = ph ? (g_vc + bh*4096) : (g_lat + bh*4096);
        __syncthreads();
        for (int i = tid*4; i < 8192; i += 1024) {
            const int rr = i >> 6, dd = i & 63;
            *(float4*)&tile[rr*68+dd] = *(const float4*)&tsrc[i];
        }
        for (int i = tid*4; i < 4096; i += 1024) {
            *(float4*)&mA[i] = *(const float4*)&Asrc[i];
            *(float4*)&mB[i] = *(const float4*)&Bsrc[i];
        }
        __syncthreads();

        float lg[32];
#pragma unroll
        for (int j = 0; j < 32; j++) lg[j] = 0.f;
        for (int d = 0; d < 64; d += 4) {
            const float4 a4 = *(const float4*)&tile[r*68 + d];
#pragma unroll
            for (int j = 0; j < 32; j++) {
                const float4 w4 = *(const float4*)&mA[(base+j)*64 + d];
                lg[j] += a4.x*w4.x + a4.y*w4.y + a4.z*w4.z + a4.w*w4.w;
            }
        }
        float mx = -1e30f;
#pragma unroll
        for (int j = 0; j < 32; j++) mx = fmaxf(mx, lg[j]);
        mx = fmaxf(mx, __shfl_xor_sync(0xffffffffu, mx, 1));
        float s = 0.f;
#pragma unroll
        for (int j = 0; j < 32; j++) { lg[j] = __expf(lg[j] - mx); s += lg[j]; }
        s += __shfl_xor_sync(0xffffffffu, s, 1);
        const float inv = 1.f / s;
#pragma unroll
        for (int j = 0; j < 32; j++) P[r*66 + base + j] = lg[j] * inv;
        __syncwarp();

        float acc[32];
#pragma unroll
        for (int j = 0; j < 32; j++) acc[j] = 0.f;
        for (int m = 0; m < 64; m++) {
            const float p = P[r*66 + m];
#pragma unroll
            for (int j = 0; j < 32; j += 4) {
                const float4 b4 = *(const float4*)&mB[m*64 + base + j];
                acc[j+0] += p*b4.x; acc[j+1] += p*b4.y; acc[j+2] += p*b4.z; acc[j+3] += p*b4.w;
            }
        }
        if (ph == 0) {
#pragma unroll
            for (int j = 0; j < 32; j++) selfv[j] = acc[j];
        } else {
            float* op = &g_mixed[((size_t)(b * N_ + n0 + r)) * C_ + h*64 + base];
#pragma unroll
            for (int j = 0; j < 32; j += 4) {
                float4 o4;
                o4.x = w*selfv[j+0] + (1.f-w)*acc[j+0];
                o4.y = w*selfv[j+1] + (1.f-w)*acc[j+1];
                o4.z = w*selfv[j+2] + (1.f-w)*acc[j+2];
                o4.w = w*selfv[j+3] + (1.f-w)*acc[j+3];
                *(float4*)&op[j] = o4;
            }
        }
    }
}

// ---------------- launch ----------------
extern "C" void kernel_launch(void* const* d_in, const int* in_sizes, int n_in,
                              void* d_out, int out_size)
{
    const float* x    = (const float*)d_in[0];
    const float* ctx  = (const float*)d_in[1];
    const float* qg   = (const float*)d_in[2];
    const float* Wx   = (const float*)d_in[3];
    const float* bx   = (const float*)d_in[4];
    const float* Wk   = (const float*)d_in[5];
    const float* bk   = (const float*)d_in[6];
    const float* Wv   = (const float*)d_in[7];
    const float* bv   = (const float*)d_in[8];
    const float* Wcq  = (const float*)d_in[9];
    const float* bcq  = (const float*)d_in[10];
    const float* Wck  = (const float*)d_in[11];
    const float* bck  = (const float*)d_in[12];
    const float* Wcv  = (const float*)d_in[13];
    const float* bcv  = (const float*)d_in[14];
    const float* smix = (const float*)d_in[15];
    const float* Wo   = (const float*)d_in[16];
    const float* bo   = (const float*)d_in[17];
    float* out = (float*)d_out;

    static bool attr_done = false;
    if (!attr_done) {
        cudaFuncSetAttribute(kvq_kernel, cudaFuncAttributeMaxDynamicSharedMemorySize, 21184*4);
        cudaFuncSetAttribute(latent_kernel, cudaFuncAttributeMaxDynamicSharedMemorySize, 16896*4);
        cudaFuncSetAttribute(dec_cross_kernel, cudaFuncAttributeMaxDynamicSharedMemorySize, 25344*4);
        attr_done = true;
    }

    gemm512_kernel<1><<<dim3(4, 256), 256>>>(x, Wx, bx, nullptr);
    kvq_kernel<<<dim3(128, 16), 256, 21184*4>>>(Wk, bk, Wv, bv, Wcq, bcq);
    ctx_kernel<<<16, 256>>>(ctx, Wck, bck, Wcv, bcv);
    enc_logits_kernel<<<dim3(128, 16), 256>>>(qg);
    softmax_stats_kernel<<<BH_ * M_, 256>>>();
    zero_lat_kernel<<<(BH_*M_*D_ + 255)/256, 256>>>();
    latent_kernel<<<dim3(16, 16), 256, 16896*4>>>();
    dec_cross_kernel<<<dim3(128, 16), 256, 25344*4>>>(qg, smix);
    gemm512_kernel<0><<<dim3(4, 256), 256>>>(nullptr, Wo, bo, out);
}

// round 5
// speedup vs baseline: 1.3448x; 1.3448x over previous
#include <cuda_runtime.h>
#include <math.h>

#define B_   2
#define N_   16384
#define C_   512
#define H_   8
#define D_   64
#define M_   64
#define SC_  64
#define BH_  (B_ * H_)
#define CH_  16          // encode chunks per bh

__device__ float g_xmid[(size_t)BH_ * N_ * D_];
__device__ float g_k   [(size_t)BH_ * N_ * D_];
__device__ float g_v   [(size_t)BH_ * N_ * D_];
__device__ float g_q   [(size_t)BH_ * N_ * D_];
__device__ float g_lat [BH_ * M_ * D_];
__device__ float g_kc  [BH_ * SC_ * D_];
__device__ float g_vc  [BH_ * SC_ * D_];
__device__ float g_mixed[(size_t)B_ * N_ * C_];
__device__ float g_pmax[BH_ * CH_ * M_];
__device__ float g_psum[BH_ * CH_ * M_];
__device__ float g_pacc[BH_ * CH_ * M_ * D_];

__device__ __forceinline__ unsigned f2tf32(float f) {
    unsigned r; asm("cvt.rna.tf32.f32 %0, %1;" : "=r"(r) : "f"(f)); return r;
}
__device__ __forceinline__ void mma_tf32(float c[4], const unsigned a[4], const unsigned b[2]) {
    asm volatile("mma.sync.aligned.m16n8k8.row.col.f32.tf32.tf32.f32 "
                 "{%0,%1,%2,%3}, {%4,%5,%6,%7}, {%8,%9}, {%0,%1,%2,%3};"
                 : "+f"(c[0]), "+f"(c[1]), "+f"(c[2]), "+f"(c[3])
                 : "r"(a[0]), "r"(a[1]), "r"(a[2]), "r"(a[3]), "r"(b[0]), "r"(b[1]));
}

// ---------------- 32768x512x512 TF32 GEMM (C = A @ W^T + b) ----------------
// MODE 1: A = Ain(x), scatter to g_xmid(B,H,N,D).  MODE 0: A = g_mixed, row-major out.
template<int MODE>
__global__ void __launch_bounds__(256) gemm512_tf32(const float* __restrict__ Ain,
                                                    const float* __restrict__ W,
                                                    const float* __restrict__ bias,
                                                    float* __restrict__ Cout)
{
    __shared__ unsigned As[128 * 20];   // [m][k] stride 20
    __shared__ unsigned Bs[128 * 20];   // [n][k] stride 20
    const float* A = (MODE == 0) ? (const float*)g_mixed : Ain;
    const int m0 = blockIdx.y * 128, n0 = blockIdx.x * 128;
    const int tid = threadIdx.x;
    const int warp = tid >> 5, lane = tid & 31;
    const int g = lane >> 2, tg = lane & 3;
    const int wm = (warp & 3) * 32, wn = (warp >> 2) * 64;
    const int lr = tid >> 2, lc = (tid & 3) * 4;

    float c[2][8][4];
#pragma unroll
    for (int mt = 0; mt < 2; mt++)
#pragma unroll
        for (int nt = 0; nt < 8; nt++)
#pragma unroll
            for (int i = 0; i < 4; i++) c[mt][nt][i] = 0.f;

    const float* Ap = A + (size_t)(m0 + lr) * C_ + lc;
    const float* Wp = W + (size_t)(n0 + lr) * C_ + lc;
    float4 pa0 = *(const float4*)(Ap);
    float4 pa1 = *(const float4*)(Ap + (size_t)64 * C_);
    float4 pb0 = *(const float4*)(Wp);
    float4 pb1 = *(const float4*)(Wp + (size_t)64 * C_);

    for (int k0 = 0; k0 < C_; k0 += 16) {
        __syncthreads();
        uint4 u;
        u.x = f2tf32(pa0.x); u.y = f2tf32(pa0.y); u.z = f2tf32(pa0.z); u.w = f2tf32(pa0.w);
        *(uint4*)&As[lr * 20 + lc] = u;
        u.x = f2tf32(pa1.x); u.y = f2tf32(pa1.y); u.z = f2tf32(pa1.z); u.w = f2tf32(pa1.w);
        *(uint4*)&As[(lr + 64) * 20 + lc] = u;
        u.x = f2tf32(pb0.x); u.y = f2tf32(pb0.y); u.z = f2tf32(pb0.z); u.w = f2tf32(pb0.w);
        *(uint4*)&Bs[lr * 20 + lc] = u;
        u.x = f2tf32(pb1.x); u.y = f2tf32(pb1.y); u.z = f2tf32(pb1.z); u.w = f2tf32(pb1.w);
        *(uint4*)&Bs[(lr + 64) * 20 + lc] = u;
        __syncthreads();
        if (k0 + 16 < C_) {
            pa0 = *(const float4*)(Ap + k0 + 16);
            pa1 = *(const float4*)(Ap + (size_t)64 * C_ + k0 + 16);
            pb0 = *(const float4*)(Wp + k0 + 16);
            pb1 = *(const float4*)(Wp + (size_t)64 * C_ + k0 + 16);
        }
#pragma unroll
        for (int ks = 0; ks < 2; ks++) {
            const int kb = ks * 8;
            unsigned a[2][4], b[8][2];
#pragma unroll
            for (int mt = 0; mt < 2; mt++) {
                const int row = wm + mt * 16;
                a[mt][0] = As[(row + g) * 20 + kb + tg];
                a[mt][1] = As[(row + g + 8) * 20 + kb + tg];
                a[mt][2] = As[(row + g) * 20 + kb + tg + 4];
                a[mt][3] = As[(row + g + 8) * 20 + kb + tg + 4];
            }
#pragma unroll
            for (int nt = 0; nt < 8; nt++) {
                const int col = wn + nt * 8 + g;
                b[nt][0] = Bs[col * 20 + kb + tg];
                b[nt][1] = Bs[col * 20 + kb + tg + 4];
            }
#pragma unroll
            for (int mt = 0; mt < 2; mt++)
#pragma unroll
                for (int nt = 0; nt < 8; nt++)
                    mma_tf32(c[mt][nt], a[mt], b[nt]);
        }
    }

#pragma unroll
    for (int mt = 0; mt < 2; mt++)
#pragma unroll
        for (int nt = 0; nt < 8; nt++) {
            const int row = m0 + wm + mt * 16 + g;
            const int col = n0 + wn + nt * 8 + tg * 2;
            const float b0 = __ldg(&bias[col]), b1 = __ldg(&bias[col + 1]);
            float2 r0 = make_float2(c[mt][nt][0] + b0, c[mt][nt][1] + b1);
            float2 r1 = make_float2(c[mt][nt][2] + b0, c[mt][nt][3] + b1);
            if (MODE == 0) {
                *(float2*)&Cout[(size_t)row * C_ + col] = r0;
                *(float2*)&Cout[(size_t)(row + 8) * C_ + col] = r1;
            } else {
                const int bb = row >> 14, h = col >> 6, d = col & 63;
                const int n = row & (N_ - 1);
                float* base = &g_xmid[(((size_t)(bb * H_ + h)) * N_) * D_ + d];
                *(float2*)&base[(size_t)n * D_] = r0;
                *(float2*)&base[(size_t)(n + 8) * D_] = r1;
            }
        }
}

// ---------------- k/v/q(head) projections, K=64, 192 outputs ----------------
__global__ void __launch_bounds__(256) kvq_kernel(const float* __restrict__ Wk, const float* __restrict__ bk,
                                                  const float* __restrict__ Wv, const float* __restrict__ bv,
                                                  const float* __restrict__ Wq, const float* __restrict__ bq)
{
    extern __shared__ float sm[];
    float* xm_s   = sm;                 // 128 x 68
    float* W_sT   = sm + 8704;          // [64][192]
    float* bias_s = W_sT + 64 * 192;    // 192

    const int bh = blockIdx.y, t0 = blockIdx.x * 128, tid = threadIdx.x;
    for (int i = tid; i < 4096; i += 256) {
        const int d = i >> 6, c = i & 63;
        W_sT[c*192 + d]       = Wk[i];
        W_sT[c*192 + 64 + d]  = Wv[i];
        W_sT[c*192 + 128 + d] = Wq[i];
    }
    if (tid < 64) { bias_s[tid] = bk[tid]; bias_s[64+tid] = bv[tid]; bias_s[128+tid] = bq[tid]; }
    const float* xp = g_xmid + ((size_t)bh * N_ + t0) * D_;
    for (int i = tid * 4; i < 8192; i += 1024) {
        const int rr = i >> 6, dd = i & 63;
        *(float4*)&xm_s[rr*68+dd] = *(const float4*)(xp + i);
    }
    __syncthreads();

    const int rx = tid & 15, ry = tid >> 4;
    float acc[8][12];
#pragma unroll
    for (int i = 0; i < 8; i++)
#pragma unroll
        for (int j = 0; j < 12; j++) acc[i][j] = 0.f;
#pragma unroll 4
    for (int kk = 0; kk < 64; kk++) {
        float a[8];
#pragma unroll
        for (int i = 0; i < 8; i++) a[i] = xm_s[(ry*8+i)*68 + kk];
        const float* wr = &W_sT[kk*192 + rx*12];
        float4 b0 = *(const float4*)(wr), b1 = *(const float4*)(wr+4), b2 = *(const float4*)(wr+8);
        float bb[12] = {b0.x,b0.y,b0.z,b0.w,b1.x,b1.y,b1.z,b1.w,b2.x,b2.y,b2.z,b2.w};
#pragma unroll
        for (int i = 0; i < 8; i++)
#pragma unroll
            for (int j = 0; j < 12; j++) acc[i][j] = fmaf(a[i], bb[j], acc[i][j]);
    }
    const size_t rowbase = (size_t)bh * N_ + t0;
#pragma unroll
    for (int i = 0; i < 8; i++) {
        const size_t row = rowbase + ry*8 + i;
#pragma unroll
        for (int j = 0; j < 12; j++) {
            const int col = rx*12 + j, mat = col >> 6, d = col & 63;
            float* op = (mat == 0) ? g_k : (mat == 1) ? g_v : g_q;
            op[row * D_ + d] = acc[i][j] + bias_s[col];
        }
    }
}

// ---------------- context kc/vc projection ----------------
__global__ void __launch_bounds__(256) ctx_kernel(const float* __restrict__ ctx,
                                                  const float* __restrict__ Wck, const float* __restrict__ bck,
                                                  const float* __restrict__ Wcv, const float* __restrict__ bcv)
{
    __shared__ float WkT[4096], WvT[4096];
    const int bh = blockIdx.x, tid = threadIdx.x;
    for (int i = tid; i < 4096; i += 256) {
        const int d = i >> 6, c = i & 63;
        WkT[c*64+d] = Wck[i];
        WvT[c*64+d] = Wcv[i];
    }
    __syncthreads();
    const float* cp = ctx + (size_t)bh * 4096;
    for (int o = tid; o < 4096; o += 256) {
        const int s = o >> 6, d = o & 63;
        float ak = bck[d], av = bcv[d];
#pragma unroll 8
        for (int c = 0; c < 64; c++) {
            const float xv = __ldg(&cp[s*64+c]);
            ak = fmaf(xv, WkT[c*64+d], ak);
            av = fmaf(xv, WvT[c*64+d], av);
        }
        g_kc[bh*4096 + o] = ak;
        g_vc[bh*4096 + o] = av;
    }
}

// ---------------- flash-style encode: latent partials over N chunks ----------------
__global__ void __launch_bounds__(256) enc_flash_kernel(const float* __restrict__ qg)
{
    extern __shared__ float sm[];
    float* qgT = sm;               // [d][m] 64x64
    float* kT  = sm + 4096;        // [d][n] 64 x 132
    float* v_s = kT + 64 * 132;    // [n][d] 128 x 64
    float* P   = v_s + 8192;       // [m][n'] 64 x 132 (n swizzled)
    const int bh = blockIdx.y, h = bh & (H_ - 1), chunk = blockIdx.x;
    const int tid = threadIdx.x, rx = tid & 15, ry = tid >> 4;

    for (int i = tid; i < 4096; i += 256) {
        const int m = i >> 6, d = i & 63;
        qgT[d * 64 + m] = qg[h * 4096 + i];
    }

    float o[4][4];
    float rmax[4], rsum[4];
#pragma unroll
    for (int i = 0; i < 4; i++) {
        rmax[i] = -1e30f; rsum[i] = 0.f;
#pragma unroll
        for (int j = 0; j < 4; j++) o[i][j] = 0.f;
    }

    const int n0 = chunk * 1024;
    for (int sub = 0; sub < 8; sub++) {
        const int nb = n0 + sub * 128;
        __syncthreads();
        const float* kp = g_k + ((size_t)bh * N_ + nb) * D_;
        {
            const int n = tid & 127;
            for (int dg = tid >> 7; dg < 16; dg += 2) {
                float4 v4 = *(const float4*)(kp + n * 64 + dg * 4);
                kT[(dg*4+0)*132+n] = v4.x; kT[(dg*4+1)*132+n] = v4.y;
                kT[(dg*4+2)*132+n] = v4.z; kT[(dg*4+3)*132+n] = v4.w;
            }
        }
        const float* vp = g_v + ((size_t)bh * N_ + nb) * D_;
        for (int i = tid * 4; i < 8192; i += 1024) *(float4*)(v_s + i) = *(const float4*)(vp + i);
        __syncthreads();

        float l[4][8];
#pragma unroll
        for (int i = 0; i < 4; i++)
#pragma unroll
            for (int j = 0; j < 8; j++) l[i][j] = 0.f;
#pragma unroll 4
        for (int kk = 0; kk < 64; kk++) {
            float4 a4 = *(const float4*)&qgT[kk*64 + ry*4];
            float4 b0 = *(const float4*)&kT[kk*132 + rx*8];
            float4 b1 = *(const float4*)&kT[kk*132 + rx*8 + 4];
            float av[4] = {a4.x,a4.y,a4.z,a4.w};
            float bv[8] = {b0.x,b0.y,b0.z,b0.w,b1.x,b1.y,b1.z,b1.w};
#pragma unroll
            for (int i = 0; i < 4; i++)
#pragma unroll
                for (int j = 0; j < 8; j++) l[i][j] = fmaf(av[i], bv[j], l[i][j]);
        }

#pragma unroll
        for (int i = 0; i < 4; i++) {
            float mx = l[i][0];
#pragma unroll
            for (int j = 1; j < 8; j++) mx = fmaxf(mx, l[i][j]);
#pragma unroll
            for (int off = 1; off < 16; off <<= 1) mx = fmaxf(mx, __shfl_xor_sync(0xffffffffu, mx, off));
            const float Mn = fmaxf(rmax[i], mx);
            const float scale = __expf(rmax[i] - Mn);
            rsum[i] *= scale;
#pragma unroll
            for (int j = 0; j < 4; j++) o[i][j] *= scale;
            float e[8], ls = 0.f;
#pragma unroll
            for (int j = 0; j < 8; j++) { e[j] = __expf(l[i][j] - Mn); ls += e[j]; }
#pragma unroll
            for (int off = 1; off < 16; off <<= 1) ls += __shfl_xor_sync(0xffffffffu, ls, off);
            rsum[i] += ls;
            rmax[i] = Mn;
            const int m = ry * 4 + i;
#pragma unroll
            for (int j = 0; j < 8; j++) {
                const int n = rx * 8 + j;
                P[m * 132 + ((n >> 3) | ((n & 7) << 4))] = e[j];
            }
        }
        __syncthreads();

#pragma unroll 4
        for (int nn = 0; nn < 128; nn++) {
            const int np = (nn >> 3) | ((nn & 7) << 4);
            float p0 = P[(ry*4+0)*132 + np];
            float p1 = P[(ry*4+1)*132 + np];
            float p2 = P[(ry*4+2)*132 + np];
            float p3 = P[(ry*4+3)*132 + np];
            float4 vv = *(const float4*)&v_s[nn*64 + rx*4];
            float bv[4] = {vv.x, vv.y, vv.z, vv.w};
#pragma unroll
            for (int j = 0; j < 4; j++) {
                o[0][j] = fmaf(p0, bv[j], o[0][j]);
                o[1][j] = fmaf(p1, bv[j], o[1][j]);
                o[2][j] = fmaf(p2, bv[j], o[2][j]);
                o[3][j] = fmaf(p3, bv[j], o[3][j]);
            }
        }
    }

    const int cidx = bh * CH_ + chunk;
#pragma unroll
    for (int i = 0; i < 4; i++) {
        const int m = ry * 4 + i;
        *(float4*)&g_pacc[((size_t)cidx * 64 + m) * 64 + rx * 4] =
            make_float4(o[i][0], o[i][1], o[i][2], o[i][3]);
        if (rx == 0) {
            g_pmax[cidx * 64 + m] = rmax[i];
            g_psum[cidx * 64 + m] = rsum[i];
        }
    }
}

// ---------------- combine encode partials -> g_lat ----------------
__global__ void __launch_bounds__(256) enc_combine_kernel()
{
    __shared__ float pm[CH_][64], ps[CH_][64], Minv[64];
    const int bh = blockIdx.x, tid = threadIdx.x;
    for (int i = tid; i < CH_ * 64; i += 256) {
        pm[i >> 6][i & 63] = g_pmax[bh * CH_ * 64 + i];
        ps[i >> 6][i & 63] = g_psum[bh * CH_ * 64 + i];
    }
    __syncthreads();
    if (tid < 64) {
        float mx = -1e30f;
#pragma unroll
        for (int c = 0; c < CH_; c++) mx = fmaxf(mx, pm[c][tid]);
        float s = 0.f;
#pragma unroll
        for (int c = 0; c < CH_; c++) {
            const float w = __expf(pm[c][tid] - mx);
            pm[c][tid] = w;
            s += w * ps[c][tid];
        }
        Minv[tid] = 1.f / s;
    }
    __syncthreads();
    for (int e = tid; e < M_ * D_; e += 256) {
        const int m = e >> 6, d = e & 63;
        float acc = 0.f;
#pragma unroll
        for (int c = 0; c < CH_; c++)
            acc += pm[c][m] * g_pacc[(((size_t)bh * CH_ + c) * 64 + m) * 64 + d];
        g_lat[bh * 4096 + e] = acc * Minv[m];
    }
}

// ---------------- fused decode + cross + sigmoid gate ----------------
__global__ void __launch_bounds__(256) dec_cross_kernel(const float* __restrict__ qg,
                                                        const float* __restrict__ smix)
{
    extern __shared__ float sm[];
    float* tile = sm;            // 128 x 68
    float* P    = sm + 8704;     // 128 x 66
    float* mA   = sm + 17152;    // 64 x 64
    float* mB   = sm + 21248;    // 64 x 64
    const int bh = blockIdx.y, b = bh >> 3, h = bh & 7;
    const int n0 = blockIdx.x * 128, tid = threadIdx.x;
    const int r = tid >> 1, half = tid & 1, base = half * 32;
    const float w = 1.f / (1.f + __expf(-smix[0]));
    float selfv[32];

    for (int ph = 0; ph < 2; ph++) {
        const float* tsrc = (ph ? g_q : g_k) + ((size_t)bh * N_ + n0) * D_;
        const float* Asrc = ph ? (g_kc + bh*4096) : (qg + h*4096);
        const float* Bsrc = ph ? (g_vc + bh*4096) : (g_lat + bh*4096);
        __syncthreads();
        for (int i = tid*4; i < 8192; i += 1024) {
            const int rr = i >> 6, dd = i & 63;
            *(float4*)&tile[rr*68+dd] = *(const float4*)&tsrc[i];
        }
        for (int i = tid*4; i < 4096; i += 1024) {
            *(float4*)&mA[i] = *(const float4*)&Asrc[i];
            *(float4*)&mB[i] = *(const float4*)&Bsrc[i];
        }
        __syncthreads();

        float lg[32];
#pragma unroll
        for (int j = 0; j < 32; j++) lg[j] = 0.f;
        for (int d = 0; d < 64; d += 4) {
            const float4 a4 = *(const float4*)&tile[r*68 + d];
#pragma unroll
            for (int j = 0; j < 32; j++) {
                const float4 w4 = *(const float4*)&mA[(base+j)*64 + d];
                lg[j] += a4.x*w4.x + a4.y*w4.y + a4.z*w4.z + a4.w*w4.w;
            }
        }
        float mx = -1e30f;
#pragma unroll
        for (int j = 0; j < 32; j++) mx = fmaxf(mx, lg[j]);
        mx = fmaxf(mx, __shfl_xor_sync(0xffffffffu, mx, 1));
        float s = 0.f;
#pragma unroll
        for (int j = 0; j < 32; j++) { lg[j] = __expf(lg[j] - mx); s += lg[j]; }
        s += __shfl_xor_sync(0xffffffffu, s, 1);
        const float inv = 1.f / s;
#pragma unroll
        for (int j = 0; j < 32; j++) P[r*66 + base + j] = lg[j] * inv;
        __syncwarp();

        float acc[32];
#pragma unroll
        for (int j = 0; j < 32; j++) acc[j] = 0.f;
        for (int m = 0; m < 64; m++) {
            const float p = P[r*66 + m];
#pragma unroll
            for (int j = 0; j < 32; j += 4) {
                const float4 b4 = *(const float4*)&mB[m*64 + base + j];
                acc[j+0] += p*b4.x; acc[j+1] += p*b4.y; acc[j+2] += p*b4.z; acc[j+3] += p*b4.w;
            }
        }
        if (ph == 0) {
#pragma unroll
            for (int j = 0; j < 32; j++) selfv[j] = acc[j];
        } else {
            float* op = &g_mixed[((size_t)(b * N_ + n0 + r)) * C_ + h*64 + base];
#pragma unroll
            for (int j = 0; j < 32; j += 4) {
                float4 o4;
                o4.x = w*selfv[j+0] + (1.f-w)*acc[j+0];
                o4.y = w*selfv[j+1] + (1.f-w)*acc[j+1];
                o4.z = w*selfv[j+2] + (1.f-w)*acc[j+2];
                o4.w = w*selfv[j+3] + (1.f-w)*acc[j+3];
                *(float4*)&op[j] = o4;
            }
        }
    }
}

// ---------------- launch ----------------
extern "C" void kernel_launch(void* const* d_in, const int* in_sizes, int n_in,
                              void* d_out, int out_size)
{
    const float* x    = (const float*)d_in[0];
    const float* ctx  = (const float*)d_in[1];
    const float* qg   = (const float*)d_in[2];
    const float* Wx   = (const float*)d_in[3];
    const float* bx   = (const float*)d_in[4];
    const float* Wk   = (const float*)d_in[5];
    const float* bk   = (const float*)d_in[6];
    const float* Wv   = (const float*)d_in[7];
    const float* bv   = (const float*)d_in[8];
    const float* Wcq  = (const float*)d_in[9];
    const float* bcq  = (const float*)d_in[10];
    const float* Wck  = (const float*)d_in[11];
    const float* bck  = (const float*)d_in[12];
    const float* Wcv  = (const float*)d_in[13];
    const float* bcv  = (const float*)d_in[14];
    const float* smix = (const float*)d_in[15];
    const float* Wo   = (const float*)d_in[16];
    const float* bo   = (const float*)d_in[17];
    float* out = (float*)d_out;

    static bool attr_done = false;
    if (!attr_done) {
        cudaFuncSetAttribute(kvq_kernel, cudaFuncAttributeMaxDynamicSharedMemorySize, 21184*4);
        cudaFuncSetAttribute(enc_flash_kernel, cudaFuncAttributeMaxDynamicSharedMemorySize, 29184*4);
        cudaFuncSetAttribute(dec_cross_kernel, cudaFuncAttributeMaxDynamicSharedMemorySize, 25344*4);
        attr_done = true;
    }

    gemm512_tf32<1><<<dim3(4, 256), 256>>>(x, Wx, bx, nullptr);
    kvq_kernel<<<dim3(128, 16), 256, 21184*4>>>(Wk, bk, Wv, bv, Wcq, bcq);
    ctx_kernel<<<16, 256>>>(ctx, Wck, bck, Wcv, bcv);
    enc_flash_kernel<<<dim3(CH_, 16), 256, 29184*4>>>(qg);
    enc_combine_kernel<<<16, 256>>>();
    dec_cross_kernel<<<dim3(128, 16), 256, 25344*4>>>(qg, smix);
    gemm512_tf32<0><<<dim3(4, 256), 256>>>(nullptr, Wo, bo, out);
}